// round 9
// baseline (speedup 1.0000x reference)
#include <cuda_runtime.h>
#include <cuda_bf16.h>
#include <cstdint>
#include <cstddef>

// ---------------- problem constants ----------------
#define N_NODES 325
#define N_BATCH 32
#define N_T 64
#define N_F 64
#define KC 32                    // k per chunk
#define NUM_KC 11                // K padded to 352
#define COUNT_TOTAL (N_BATCH * N_NODES * N_T)

// ---------------- device scratch ----------------
__device__ float g_dis[N_NODES];
// A tiles pre-formatted in the exact smem image: [mt][kc][128 r][40 kw] bf16
// (row = 32 data bf16 + 8 pad = 80 bytes = 20 words; conflict-free fragment reads)
__device__ __nv_bfloat16 g_ahi_t[3 * NUM_KC * 128 * 40];
__device__ __nv_bfloat16 g_alo_t[3 * NUM_KC * 128 * 40];
__device__ float g_psum[16][N_F];
__device__ float g_psq[16][N_F];
__device__ float g_scale[N_F];
__device__ float g_shift[N_F];

// ---------------- helpers ----------------
static __device__ __forceinline__ uint32_t smem_addr_u32(const void* p) {
    uint32_t a;
    asm("{ .reg .u64 t; cvta.to.shared.u64 t, %1; cvt.u32.u64 %0, t; }" : "=r"(a) : "l"(p));
    return a;
}
#define CP_ASYNC16(dst_u32, src_ptr) \
    asm volatile("cp.async.cg.shared.global [%0], [%1], 16;" :: "r"(dst_u32), "l"(src_ptr) : "memory")
#define CP_COMMIT() asm volatile("cp.async.commit_group;" ::: "memory")
#define CP_WAIT0()  asm volatile("cp.async.wait_group 0;" ::: "memory")

// mma.sync m16n8k16 bf16 (sm_80+; synchronous, no barrier/hang surface)
static __device__ __forceinline__ void mma16816(float& d0, float& d1, float& d2, float& d3,
                                                uint32_t a0, uint32_t a1, uint32_t a2, uint32_t a3,
                                                uint32_t b0, uint32_t b1) {
    asm volatile("mma.sync.aligned.m16n8k16.row.col.f32.bf16.bf16.f32 "
        "{%0,%1,%2,%3}, {%4,%5,%6,%7}, {%8,%9}, {%0,%1,%2,%3};"
        : "+f"(d0), "+f"(d1), "+f"(d2), "+f"(d3)
        : "r"(a0), "r"(a1), "r"(a2), "r"(a3), "r"(b0), "r"(b1));
}

// ---- packed fp32x2 helpers (epilogue; proven) ----
static __device__ __forceinline__ unsigned long long pk2(float lo, float hi) {
    unsigned long long r;
    asm("mov.b64 %0, {%1, %2};" : "=l"(r) : "f"(lo), "f"(hi));
    return r;
}
static __device__ __forceinline__ void upk2(unsigned long long v, float& lo, float& hi) {
    asm("mov.b64 {%0, %1}, %2;" : "=f"(lo), "=f"(hi) : "l"(v));
}
static __device__ __forceinline__ unsigned long long ffma2(unsigned long long a,
                                                           unsigned long long b,
                                                           unsigned long long c) {
    unsigned long long d;
    asm("fma.rn.f32x2 %0, %1, %2, %3;" : "=l"(d) : "l"(a), "l"(b), "l"(c));
    return d;
}

// ---------------- prep kernels ----------------
__global__ void prep_deg(const float* __restrict__ adj) {
    int m = threadIdx.x;
    if (m < N_NODES) {
        float s = 1.0f;
        const float* row = adj + (size_t)m * N_NODES;
        for (int n = 0; n < N_NODES; n++) s += row[n];
        g_dis[m] = (s > 0.f) ? rsqrtf(s) : 0.f;
    }
    for (int i = threadIdx.x; i < 16 * N_F; i += blockDim.x) {
        (&g_psum[0][0])[i] = 0.f;
        (&g_psq[0][0])[i]  = 0.f;
    }
}

__global__ void prep_at(const float* __restrict__ adj) {
    int idx = blockIdx.x * blockDim.x + threadIdx.x;
    if (idx >= 3 * NUM_KC * 128 * 40) return;
    int kw = idx % 40;
    int r  = (idx / 40) & 127;
    int kc = (idx / (40 * 128)) % NUM_KC;
    int mt = idx / (40 * 128 * NUM_KC);
    int m = mt * 128 + r;
    int k = kc * KC + kw;
    float v = 0.f;
    if (kw < KC && m < N_NODES && k < N_NODES) {
        float a = adj[m * N_NODES + k] + (m == k ? 1.f : 0.f);
        v = g_dis[m] * a * g_dis[k];
    }
    __nv_bfloat16 h = __float2bfloat16_rn(v);
    g_ahi_t[idx] = h;
    g_alo_t[idx] = __float2bfloat16_rn(v - __bfloat162float(h));
}

// ---------------- main fused kernel ----------------
// Block (mt, t, b): Y [128 m][64 f] = a_norm[m,:] @ x[b,:,t,:], K=352 (11x32).
// Double-buffered: cp.async A tiles + register-prefetched X, one sync/chunk.
// smem buffers (x2): AHI@0 (10240) ALO@10240 XHI@20480 (5120) XLO@25600 | 30720
// epilogue reuse: Ys [128][68] f32 @0 (34816B), Ws @34816 (16384B).
#define BUFB 30720
#define OFF_AHI 0
#define OFF_ALO 10240
#define OFF_XHI 20480
#define OFF_XLO 25600
#define OFF_WS  34816
#define SMEM_TOTAL 61440
#define YS_STRIDE 68

__global__ __launch_bounds__(256, 2) void gcn_mma(const float* __restrict__ x,
                                                  const float* __restrict__ weight,
                                                  float* __restrict__ out) {
    extern __shared__ char smem[];
    const uint32_t sb = smem_addr_u32(smem);
    const int mt = blockIdx.x;   // 0..2
    const int t  = blockIdx.y;   // 0..63
    const int b  = blockIdx.z;   // 0..31
    const int tid = threadIdx.x;
    const int wid = tid >> 5;
    const int lid = tid & 31;
    const int g   = lid >> 2;    // fragment group row
    const int t4  = lid & 3;     // fragment k-pair lane
    const int wm  = wid & 3;     // warp m tile (32 rows)
    const int wn  = wid >> 2;    // warp n tile (32 f-cols)

    // X loader mapping: thread -> (k pair, f quad)
    const int kp = tid >> 4;     // 0..15 -> k rows 2kp, 2kp+1
    const int fq = tid & 15;     // f quad base

    const char* ahi_base = (const char*)(g_ahi_t + (size_t)(mt * NUM_KC) * (128 * 40));
    const char* alo_base = (const char*)(g_alo_t + (size_t)(mt * NUM_KC) * (128 * 40));
    const float* xb = x + (((size_t)b * N_NODES) * N_T + t) * N_F;   // + k*4096 + f

    float d[2][4][4];
#pragma unroll
    for (int mi = 0; mi < 2; mi++)
#pragma unroll
        for (int nj = 0; nj < 4; nj++)
#pragma unroll
            for (int c = 0; c < 4; c++) d[mi][nj][c] = 0.f;

    float pv0[4], pv1[4];        // prefetched X rows (next chunk)

    // ---- prologue: A chunk 0 via cp.async, X chunk 0 via regs ----
    {
        const char* hsrc = ahi_base;
        const char* lsrc = alo_base;
#pragma unroll
        for (int j = 0; j < 3; j++) {
            int e = tid + j * 256;
            if (e < 640) {
                CP_ASYNC16(sb + OFF_AHI + e * 16, hsrc + e * 16);
                CP_ASYNC16(sb + OFF_ALO + e * 16, lsrc + e * 16);
            }
        }
        CP_COMMIT();
        int gk0 = 2 * kp;
        float4 va = make_float4(0.f, 0.f, 0.f, 0.f), vc = va;
        if (gk0 < N_NODES)     va = *(const float4*)&xb[(size_t)gk0 * (N_T * N_F) + fq * 4];
        if (gk0 + 1 < N_NODES) vc = *(const float4*)&xb[(size_t)(gk0 + 1) * (N_T * N_F) + fq * 4];
        pv0[0] = va.x; pv0[1] = va.y; pv0[2] = va.z; pv0[3] = va.w;
        pv1[0] = vc.x; pv1[1] = vc.y; pv1[2] = vc.z; pv1[3] = vc.w;
        // convert + store X chunk 0 into buf0
        uint32_t* XH = (uint32_t*)(smem + OFF_XHI);
        uint32_t* XL = (uint32_t*)(smem + OFF_XLO);
#pragma unroll
        for (int i = 0; i < 4; i++) {
            int ip = (i + fq) & 3;
            int f = fq * 4 + ip;
            __nv_bfloat16 h0 = __float2bfloat16_rn(pv0[ip]);
            __nv_bfloat16 h1 = __float2bfloat16_rn(pv1[ip]);
            __nv_bfloat16 l0 = __float2bfloat16_rn(pv0[ip] - __bfloat162float(h0));
            __nv_bfloat16 l1 = __float2bfloat16_rn(pv1[ip] - __bfloat162float(h1));
            XH[f * 20 + kp] = (uint32_t)__bfloat16_as_ushort(h0) |
                              ((uint32_t)__bfloat16_as_ushort(h1) << 16);
            XL[f * 20 + kp] = (uint32_t)__bfloat16_as_ushort(l0) |
                              ((uint32_t)__bfloat16_as_ushort(l1) << 16);
        }
        CP_WAIT0();
    }
    __syncthreads();

    // ---- main loop ----
    for (int kc = 0; kc < NUM_KC; kc++) {
        const int curo = (kc & 1) * BUFB;
        const int nxto = ((kc + 1) & 1) * BUFB;
        const bool have_next = (kc + 1 < NUM_KC);

        if (have_next) {
            // issue next A tile copy into alternate buffer (async, hidden by MMA)
            const char* hsrc = ahi_base + (size_t)(kc + 1) * 10240;
            const char* lsrc = alo_base + (size_t)(kc + 1) * 10240;
#pragma unroll
            for (int j = 0; j < 3; j++) {
                int e = tid + j * 256;
                if (e < 640) {
                    CP_ASYNC16(sb + nxto + OFF_AHI + e * 16, hsrc + e * 16);
                    CP_ASYNC16(sb + nxto + OFF_ALO + e * 16, lsrc + e * 16);
                }
            }
            CP_COMMIT();
            // issue next X global loads (regs; latency overlaps MMA below)
            int gk0 = (kc + 1) * KC + 2 * kp;
            float4 va = make_float4(0.f, 0.f, 0.f, 0.f), vc = va;
            if (gk0 < N_NODES)     va = *(const float4*)&xb[(size_t)gk0 * (N_T * N_F) + fq * 4];
            if (gk0 + 1 < N_NODES) vc = *(const float4*)&xb[(size_t)(gk0 + 1) * (N_T * N_F) + fq * 4];
            pv0[0] = va.x; pv0[1] = va.y; pv0[2] = va.z; pv0[3] = va.w;
            pv1[0] = vc.x; pv1[1] = vc.y; pv1[2] = vc.z; pv1[3] = vc.w;
        }

        const uint32_t* AH = (const uint32_t*)(smem + curo + OFF_AHI);
        const uint32_t* AL = (const uint32_t*)(smem + curo + OFF_ALO);
        const uint32_t* XH = (const uint32_t*)(smem + curo + OFF_XHI);
        const uint32_t* XL = (const uint32_t*)(smem + curo + OFF_XLO);

#pragma unroll
        for (int h = 0; h < 2; h++) {      // two k16 steps per 32-k chunk
            const int cb = h * 8;
            uint32_t ah[2][4], al[2][4], bh[4][2], bl[4][2];
#pragma unroll
            for (int mi = 0; mi < 2; mi++) {
                int r0 = (wm * 32 + mi * 16 + g) * 20 + t4 + cb;
                int r1 = (wm * 32 + mi * 16 + 8 + g) * 20 + t4 + cb;
                ah[mi][0] = AH[r0]; ah[mi][1] = AH[r1]; ah[mi][2] = AH[r0 + 4]; ah[mi][3] = AH[r1 + 4];
                al[mi][0] = AL[r0]; al[mi][1] = AL[r1]; al[mi][2] = AL[r0 + 4]; al[mi][3] = AL[r1 + 4];
            }
#pragma unroll
            for (int nj = 0; nj < 4; nj++) {
                int w0 = (wn * 32 + nj * 8 + g) * 20 + t4 + cb;
                bh[nj][0] = XH[w0]; bh[nj][1] = XH[w0 + 4];
                bl[nj][0] = XL[w0]; bl[nj][1] = XL[w0 + 4];
            }
#pragma unroll
            for (int mi = 0; mi < 2; mi++)
#pragma unroll
                for (int nj = 0; nj < 4; nj++)
                    mma16816(d[mi][nj][0], d[mi][nj][1], d[mi][nj][2], d[mi][nj][3],
                             ah[mi][0], ah[mi][1], ah[mi][2], ah[mi][3], bh[nj][0], bh[nj][1]);
#pragma unroll
            for (int mi = 0; mi < 2; mi++)
#pragma unroll
                for (int nj = 0; nj < 4; nj++)
                    mma16816(d[mi][nj][0], d[mi][nj][1], d[mi][nj][2], d[mi][nj][3],
                             ah[mi][0], ah[mi][1], ah[mi][2], ah[mi][3], bl[nj][0], bl[nj][1]);
#pragma unroll
            for (int mi = 0; mi < 2; mi++)
#pragma unroll
                for (int nj = 0; nj < 4; nj++)
                    mma16816(d[mi][nj][0], d[mi][nj][1], d[mi][nj][2], d[mi][nj][3],
                             al[mi][0], al[mi][1], al[mi][2], al[mi][3], bh[nj][0], bh[nj][1]);
        }

        if (have_next) {
            // convert + store prefetched X into alternate buffer (nobody reads it
            // until after the barrier below)
            uint32_t* XHn = (uint32_t*)(smem + nxto + OFF_XHI);
            uint32_t* XLn = (uint32_t*)(smem + nxto + OFF_XLO);
#pragma unroll
            for (int i = 0; i < 4; i++) {
                int ip = (i + fq) & 3;
                int f = fq * 4 + ip;
                __nv_bfloat16 h0 = __float2bfloat16_rn(pv0[ip]);
                __nv_bfloat16 h1 = __float2bfloat16_rn(pv1[ip]);
                __nv_bfloat16 l0 = __float2bfloat16_rn(pv0[ip] - __bfloat162float(h0));
                __nv_bfloat16 l1 = __float2bfloat16_rn(pv1[ip] - __bfloat162float(h1));
                XHn[f * 20 + kp] = (uint32_t)__bfloat16_as_ushort(h0) |
                                   ((uint32_t)__bfloat16_as_ushort(h1) << 16);
                XLn[f * 20 + kp] = (uint32_t)__bfloat16_as_ushort(l0) |
                                   ((uint32_t)__bfloat16_as_ushort(l1) << 16);
            }
            CP_WAIT0();
        }
        __syncthreads();
    }

    // ---- stage Y into smem (fragment layout -> row-major) ----
    float* Ys = (float*)smem;
#pragma unroll
    for (int mi = 0; mi < 2; mi++)
#pragma unroll
        for (int nj = 0; nj < 4; nj++) {
            int row = wm * 32 + mi * 16 + g;
            int col = wn * 32 + nj * 8 + 2 * t4;
            *(float2*)&Ys[row * YS_STRIDE + col]       = make_float2(d[mi][nj][0], d[mi][nj][1]);
            *(float2*)&Ys[(row + 8) * YS_STRIDE + col] = make_float2(d[mi][nj][2], d[mi][nj][3]);
        }
    float* Ws = (float*)(smem + OFF_WS);
    for (int i = tid; i < 64 * 64; i += 256) Ws[i] = weight[i];
    __syncthreads();

    // ---- Z = Y @ W (fp32 f32x2), BN partials, store (proven) ----
    const int tx = tid & 15;
    const int ty = tid >> 4;
    const unsigned long long z0 = pk2(0.f, 0.f);
    unsigned long long zp[8][2];
#pragma unroll
    for (int i = 0; i < 8; i++) { zp[i][0] = z0; zp[i][1] = z0; }

#pragma unroll 4
    for (int f = 0; f < 64; f++) {
        float4 w = *(const float4*)&Ws[f * 64 + tx * 4];
        unsigned long long w01 = pk2(w.x, w.y);
        unsigned long long w23 = pk2(w.z, w.w);
#pragma unroll
        for (int i = 0; i < 8; i++) {
            float yv = Ys[(ty * 8 + i) * YS_STRIDE + f];
            unsigned long long yy = pk2(yv, yv);
            zp[i][0] = ffma2(yy, w01, zp[i][0]);
            zp[i][1] = ffma2(yy, w23, zp[i][1]);
        }
    }

    float csum[4] = {0.f, 0.f, 0.f, 0.f};
    float csq[4]  = {0.f, 0.f, 0.f, 0.f};
#pragma unroll
    for (int i = 0; i < 8; i++) {
        float v0, v1, v2, v3;
        upk2(zp[i][0], v0, v1);
        upk2(zp[i][1], v2, v3);
        csum[0] += v0; csq[0] += v0 * v0;
        csum[1] += v1; csq[1] += v1 * v1;
        csum[2] += v2; csq[2] += v2 * v2;
        csum[3] += v3; csq[3] += v3 * v3;
        int gm = mt * 128 + ty * 8 + i;
        if (gm < N_NODES) {
            size_t o = (((size_t)b * N_NODES + gm) * N_T + t) * N_F + tx * 4;
            *(float4*)&out[o] = make_float4(v0, v1, v2, v3);
        }
    }

    __syncthreads();
    float* red = Ws;
    if (tid < 128) red[tid] = 0.f;
    __syncthreads();
#pragma unroll
    for (int j = 0; j < 4; j++) {
        atomicAdd(&red[tx * 4 + j], csum[j]);
        atomicAdd(&red[64 + tx * 4 + j], csq[j]);
    }
    __syncthreads();
    if (tid < 64) {
        int slab = (blockIdx.x + 3 * blockIdx.y) & 15;
        atomicAdd(&g_psum[slab][tid], red[tid]);
        atomicAdd(&g_psq[slab][tid],  red[64 + tid]);
    }
}

// ---------------- BN finalize + apply (proven) ----------------
__global__ void bn_finalize(const float* __restrict__ gamma, const float* __restrict__ beta) {
    int c = threadIdx.x;
    if (c >= N_F) return;
    float s = 0.f, q = 0.f;
    for (int i = 0; i < 16; i++) { s += g_psum[i][c]; q += g_psq[i][c]; }
    float inv  = 1.f / (float)COUNT_TOTAL;
    float mean = s * inv;
    float var  = q * inv - mean * mean;
    float sc   = gamma[c] * rsqrtf(var + 1e-5f);
    g_scale[c] = sc;
    g_shift[c] = beta[c] - mean * sc;
}

__global__ void bn_apply(float* __restrict__ out) {
    __shared__ float sc[N_F], sh[N_F];
    if (threadIdx.x < N_F) {
        sc[threadIdx.x] = g_scale[threadIdx.x];
        sh[threadIdx.x] = g_shift[threadIdx.x];
    }
    __syncthreads();
    size_t i = (size_t)blockIdx.x * blockDim.x + threadIdx.x;
    size_t e = i * 4;
    if (e >= (size_t)N_BATCH * N_NODES * N_T * N_F) return;
    int fb = (int)(e & 63);
    float4 v = *(const float4*)&out[e];
    float4 r;
    r.x = fmaxf(v.x * sc[fb + 0] + sh[fb + 0], 0.f);
    r.y = fmaxf(v.y * sc[fb + 1] + sh[fb + 1], 0.f);
    r.z = fmaxf(v.z * sc[fb + 2] + sh[fb + 2], 0.f);
    r.w = fmaxf(v.w * sc[fb + 3] + sh[fb + 3], 0.f);
    *(float4*)&out[e] = r;
}

extern "C" void kernel_launch(void* const* d_in, const int* in_sizes, int n_in,
                              void* d_out, int out_size) {
    const float *x = nullptr, *adj = nullptr, *w = nullptr, *gamma = nullptr, *beta = nullptr;
    for (int i = 0; i < n_in; i++) {
        int s = in_sizes[i];
        if      (s == N_BATCH * N_NODES * N_T * N_F) x   = (const float*)d_in[i];
        else if (s == N_NODES * N_NODES)             adj = (const float*)d_in[i];
        else if (s == N_F * N_F)                     w   = (const float*)d_in[i];
        else if (s == N_F) { if (!gamma) gamma = (const float*)d_in[i]; else beta = (const float*)d_in[i]; }
    }
    float* out = (float*)d_out;

    cudaFuncSetAttribute(gcn_mma, cudaFuncAttributeMaxDynamicSharedMemorySize, SMEM_TOTAL);

    prep_deg<<<1, 352>>>(adj);
    prep_at<<<(3 * NUM_KC * 128 * 40 + 255) / 256, 256>>>(adj);
    // mt fastest: the 3 m-tile blocks of one (b,t) share the X slice via L2;
    // A tiles (660KB x2) stay L2-resident across the whole launch.
    gcn_mma<<<dim3(3, 64, 32), 256, SMEM_TOTAL>>>(x, w, out);
    bn_finalize<<<1, 64>>>(gamma, beta);
    bn_apply<<<41600, 256>>>(out);
}

// round 10
// speedup vs baseline: 1.0000x; 1.0000x over previous
#include <cuda_runtime.h>
#include <cuda_bf16.h>
#include <cstdint>
#include <cstddef>

// ---------------- problem constants ----------------
#define N_NODES 325
#define N_BATCH 32
#define N_T 64
#define N_F 64
#define KC 32                    // k per chunk
#define NUM_KC 11                // K padded to 352
#define COUNT_TOTAL (N_BATCH * N_NODES * N_T)

// ---------------- device scratch ----------------
__device__ float g_dis[N_NODES];
// A tiles pre-formatted in the exact smem image: [mt][kc][128 r][40 kw] bf16
// (row = 32 data bf16 + 8 pad = 80 bytes = 20 words; conflict-free fragment reads)
__device__ __nv_bfloat16 g_ahi_t[3 * NUM_KC * 128 * 40];
__device__ __nv_bfloat16 g_alo_t[3 * NUM_KC * 128 * 40];
__device__ float g_psum[16][N_F];
__device__ float g_psq[16][N_F];
__device__ float g_scale[N_F];
__device__ float g_shift[N_F];

// ---------------- helpers ----------------
static __device__ __forceinline__ uint32_t smem_addr_u32(const void* p) {
    uint32_t a;
    asm("{ .reg .u64 t; cvta.to.shared.u64 t, %1; cvt.u32.u64 %0, t; }" : "=r"(a) : "l"(p));
    return a;
}
#define CP_ASYNC16(dst_u32, src_ptr) \
    asm volatile("cp.async.cg.shared.global [%0], [%1], 16;" :: "r"(dst_u32), "l"(src_ptr) : "memory")
#define CP_COMMIT() asm volatile("cp.async.commit_group;" ::: "memory")
#define CP_WAIT0()  asm volatile("cp.async.wait_group 0;" ::: "memory")

// mma.sync m16n8k16 bf16 (sm_80+; synchronous, no barrier/hang surface)
static __device__ __forceinline__ void mma16816(float& d0, float& d1, float& d2, float& d3,
                                                uint32_t a0, uint32_t a1, uint32_t a2, uint32_t a3,
                                                uint32_t b0, uint32_t b1) {
    asm volatile("mma.sync.aligned.m16n8k16.row.col.f32.bf16.bf16.f32 "
        "{%0,%1,%2,%3}, {%4,%5,%6,%7}, {%8,%9}, {%0,%1,%2,%3};"
        : "+f"(d0), "+f"(d1), "+f"(d2), "+f"(d3)
        : "r"(a0), "r"(a1), "r"(a2), "r"(a3), "r"(b0), "r"(b1));
}

// ---- packed fp32x2 helpers (epilogue; proven) ----
static __device__ __forceinline__ unsigned long long pk2(float lo, float hi) {
    unsigned long long r;
    asm("mov.b64 %0, {%1, %2};" : "=l"(r) : "f"(lo), "f"(hi));
    return r;
}
static __device__ __forceinline__ void upk2(unsigned long long v, float& lo, float& hi) {
    asm("mov.b64 {%0, %1}, %2;" : "=f"(lo), "=f"(hi) : "l"(v));
}
static __device__ __forceinline__ unsigned long long ffma2(unsigned long long a,
                                                           unsigned long long b,
                                                           unsigned long long c) {
    unsigned long long d;
    asm("fma.rn.f32x2 %0, %1, %2, %3;" : "=l"(d) : "l"(a), "l"(b), "l"(c));
    return d;
}

// ---------------- prep kernels ----------------
__global__ void prep_deg(const float* __restrict__ adj) {
    int m = threadIdx.x;
    if (m < N_NODES) {
        float s = 1.0f;
        const float* row = adj + (size_t)m * N_NODES;
        for (int n = 0; n < N_NODES; n++) s += row[n];
        g_dis[m] = (s > 0.f) ? rsqrtf(s) : 0.f;
    }
    for (int i = threadIdx.x; i < 16 * N_F; i += blockDim.x) {
        (&g_psum[0][0])[i] = 0.f;
        (&g_psq[0][0])[i]  = 0.f;
    }
}

__global__ void prep_at(const float* __restrict__ adj) {
    int idx = blockIdx.x * blockDim.x + threadIdx.x;
    if (idx >= 3 * NUM_KC * 128 * 40) return;
    int kw = idx % 40;
    int r  = (idx / 40) & 127;
    int kc = (idx / (40 * 128)) % NUM_KC;
    int mt = idx / (40 * 128 * NUM_KC);
    int m = mt * 128 + r;
    int k = kc * KC + kw;
    float v = 0.f;
    if (kw < KC && m < N_NODES && k < N_NODES) {
        float a = adj[m * N_NODES + k] + (m == k ? 1.f : 0.f);
        v = g_dis[m] * a * g_dis[k];
    }
    __nv_bfloat16 h = __float2bfloat16_rn(v);
    g_ahi_t[idx] = h;
    g_alo_t[idx] = __float2bfloat16_rn(v - __bfloat162float(h));
}

// ---------------- main fused kernel ----------------
// Block (mt, t, b): Y [128 m][64 f] = a_norm[m,:] @ x[b,:,t,:], K=352 (11x32).
// Double-buffered: cp.async A tiles + register-prefetched X, one sync/chunk.
// smem buffers (x2): AHI@0 (10240) ALO@10240 XHI@20480 (5120) XLO@25600 | 30720
// epilogue reuse: Ys [128][68] f32 @0 (34816B), Ws @34816 (16384B).
#define BUFB 30720
#define OFF_AHI 0
#define OFF_ALO 10240
#define OFF_XHI 20480
#define OFF_XLO 25600
#define OFF_WS  34816
#define SMEM_TOTAL 61440
#define YS_STRIDE 68

__global__ __launch_bounds__(256, 2) void gcn_mma(const float* __restrict__ x,
                                                  const float* __restrict__ weight,
                                                  float* __restrict__ out) {
    extern __shared__ char smem[];
    const uint32_t sb = smem_addr_u32(smem);
    const int mt = blockIdx.x;   // 0..2
    const int t  = blockIdx.y;   // 0..63
    const int b  = blockIdx.z;   // 0..31
    const int tid = threadIdx.x;
    const int wid = tid >> 5;
    const int lid = tid & 31;
    const int g   = lid >> 2;    // fragment group row
    const int t4  = lid & 3;     // fragment k-pair lane
    const int wm  = wid & 3;     // warp m tile (32 rows)
    const int wn  = wid >> 2;    // warp n tile (32 f-cols)

    // X loader mapping: thread -> (k pair, f quad)
    const int kp = tid >> 4;     // 0..15 -> k rows 2kp, 2kp+1
    const int fq = tid & 15;     // f quad base

    const char* ahi_base = (const char*)(g_ahi_t + (size_t)(mt * NUM_KC) * (128 * 40));
    const char* alo_base = (const char*)(g_alo_t + (size_t)(mt * NUM_KC) * (128 * 40));
    const float* xb = x + (((size_t)b * N_NODES) * N_T + t) * N_F;   // + k*4096 + f

    float d[2][4][4];
#pragma unroll
    for (int mi = 0; mi < 2; mi++)
#pragma unroll
        for (int nj = 0; nj < 4; nj++)
#pragma unroll
            for (int c = 0; c < 4; c++) d[mi][nj][c] = 0.f;

    float pv0[4], pv1[4];        // prefetched X rows (next chunk)

    // ---- prologue: A chunk 0 via cp.async, X chunk 0 via regs ----
    {
        const char* hsrc = ahi_base;
        const char* lsrc = alo_base;
#pragma unroll
        for (int j = 0; j < 3; j++) {
            int e = tid + j * 256;
            if (e < 640) {
                CP_ASYNC16(sb + OFF_AHI + e * 16, hsrc + e * 16);
                CP_ASYNC16(sb + OFF_ALO + e * 16, lsrc + e * 16);
            }
        }
        CP_COMMIT();
        int gk0 = 2 * kp;
        float4 va = make_float4(0.f, 0.f, 0.f, 0.f), vc = va;
        if (gk0 < N_NODES)     va = *(const float4*)&xb[(size_t)gk0 * (N_T * N_F) + fq * 4];
        if (gk0 + 1 < N_NODES) vc = *(const float4*)&xb[(size_t)(gk0 + 1) * (N_T * N_F) + fq * 4];
        pv0[0] = va.x; pv0[1] = va.y; pv0[2] = va.z; pv0[3] = va.w;
        pv1[0] = vc.x; pv1[1] = vc.y; pv1[2] = vc.z; pv1[3] = vc.w;
        // convert + store X chunk 0 into buf0
        uint32_t* XH = (uint32_t*)(smem + OFF_XHI);
        uint32_t* XL = (uint32_t*)(smem + OFF_XLO);
#pragma unroll
        for (int i = 0; i < 4; i++) {
            int ip = (i + fq) & 3;
            int f = fq * 4 + ip;
            __nv_bfloat16 h0 = __float2bfloat16_rn(pv0[ip]);
            __nv_bfloat16 h1 = __float2bfloat16_rn(pv1[ip]);
            __nv_bfloat16 l0 = __float2bfloat16_rn(pv0[ip] - __bfloat162float(h0));
            __nv_bfloat16 l1 = __float2bfloat16_rn(pv1[ip] - __bfloat162float(h1));
            XH[f * 20 + kp] = (uint32_t)__bfloat16_as_ushort(h0) |
                              ((uint32_t)__bfloat16_as_ushort(h1) << 16);
            XL[f * 20 + kp] = (uint32_t)__bfloat16_as_ushort(l0) |
                              ((uint32_t)__bfloat16_as_ushort(l1) << 16);
        }
        CP_WAIT0();
    }
    __syncthreads();

    // ---- main loop ----
    for (int kc = 0; kc < NUM_KC; kc++) {
        const int curo = (kc & 1) * BUFB;
        const int nxto = ((kc + 1) & 1) * BUFB;
        const bool have_next = (kc + 1 < NUM_KC);

        if (have_next) {
            // issue next A tile copy into alternate buffer (async, hidden by MMA)
            const char* hsrc = ahi_base + (size_t)(kc + 1) * 10240;
            const char* lsrc = alo_base + (size_t)(kc + 1) * 10240;
#pragma unroll
            for (int j = 0; j < 3; j++) {
                int e = tid + j * 256;
                if (e < 640) {
                    CP_ASYNC16(sb + nxto + OFF_AHI + e * 16, hsrc + e * 16);
                    CP_ASYNC16(sb + nxto + OFF_ALO + e * 16, lsrc + e * 16);
                }
            }
            CP_COMMIT();
            // issue next X global loads (regs; latency overlaps MMA below)
            int gk0 = (kc + 1) * KC + 2 * kp;
            float4 va = make_float4(0.f, 0.f, 0.f, 0.f), vc = va;
            if (gk0 < N_NODES)     va = *(const float4*)&xb[(size_t)gk0 * (N_T * N_F) + fq * 4];
            if (gk0 + 1 < N_NODES) vc = *(const float4*)&xb[(size_t)(gk0 + 1) * (N_T * N_F) + fq * 4];
            pv0[0] = va.x; pv0[1] = va.y; pv0[2] = va.z; pv0[3] = va.w;
            pv1[0] = vc.x; pv1[1] = vc.y; pv1[2] = vc.z; pv1[3] = vc.w;
        }

        const uint32_t* AH = (const uint32_t*)(smem + curo + OFF_AHI);
        const uint32_t* AL = (const uint32_t*)(smem + curo + OFF_ALO);
        const uint32_t* XH = (const uint32_t*)(smem + curo + OFF_XHI);
        const uint32_t* XL = (const uint32_t*)(smem + curo + OFF_XLO);

#pragma unroll
        for (int h = 0; h < 2; h++) {      // two k16 steps per 32-k chunk
            const int cb = h * 8;
            uint32_t ah[2][4], al[2][4], bh[4][2], bl[4][2];
#pragma unroll
            for (int mi = 0; mi < 2; mi++) {
                int r0 = (wm * 32 + mi * 16 + g) * 20 + t4 + cb;
                int r1 = (wm * 32 + mi * 16 + 8 + g) * 20 + t4 + cb;
                ah[mi][0] = AH[r0]; ah[mi][1] = AH[r1]; ah[mi][2] = AH[r0 + 4]; ah[mi][3] = AH[r1 + 4];
                al[mi][0] = AL[r0]; al[mi][1] = AL[r1]; al[mi][2] = AL[r0 + 4]; al[mi][3] = AL[r1 + 4];
            }
#pragma unroll
            for (int nj = 0; nj < 4; nj++) {
                int w0 = (wn * 32 + nj * 8 + g) * 20 + t4 + cb;
                bh[nj][0] = XH[w0]; bh[nj][1] = XH[w0 + 4];
                bl[nj][0] = XL[w0]; bl[nj][1] = XL[w0 + 4];
            }
#pragma unroll
            for (int mi = 0; mi < 2; mi++)
#pragma unroll
                for (int nj = 0; nj < 4; nj++)
                    mma16816(d[mi][nj][0], d[mi][nj][1], d[mi][nj][2], d[mi][nj][3],
                             ah[mi][0], ah[mi][1], ah[mi][2], ah[mi][3], bh[nj][0], bh[nj][1]);
#pragma unroll
            for (int mi = 0; mi < 2; mi++)
#pragma unroll
                for (int nj = 0; nj < 4; nj++)
                    mma16816(d[mi][nj][0], d[mi][nj][1], d[mi][nj][2], d[mi][nj][3],
                             ah[mi][0], ah[mi][1], ah[mi][2], ah[mi][3], bl[nj][0], bl[nj][1]);
#pragma unroll
            for (int mi = 0; mi < 2; mi++)
#pragma unroll
                for (int nj = 0; nj < 4; nj++)
                    mma16816(d[mi][nj][0], d[mi][nj][1], d[mi][nj][2], d[mi][nj][3],
                             al[mi][0], al[mi][1], al[mi][2], al[mi][3], bh[nj][0], bh[nj][1]);
        }

        if (have_next) {
            // convert + store prefetched X into alternate buffer (nobody reads it
            // until after the barrier below)
            uint32_t* XHn = (uint32_t*)(smem + nxto + OFF_XHI);
            uint32_t* XLn = (uint32_t*)(smem + nxto + OFF_XLO);
#pragma unroll
            for (int i = 0; i < 4; i++) {
                int ip = (i + fq) & 3;
                int f = fq * 4 + ip;
                __nv_bfloat16 h0 = __float2bfloat16_rn(pv0[ip]);
                __nv_bfloat16 h1 = __float2bfloat16_rn(pv1[ip]);
                __nv_bfloat16 l0 = __float2bfloat16_rn(pv0[ip] - __bfloat162float(h0));
                __nv_bfloat16 l1 = __float2bfloat16_rn(pv1[ip] - __bfloat162float(h1));
                XHn[f * 20 + kp] = (uint32_t)__bfloat16_as_ushort(h0) |
                                   ((uint32_t)__bfloat16_as_ushort(h1) << 16);
                XLn[f * 20 + kp] = (uint32_t)__bfloat16_as_ushort(l0) |
                                   ((uint32_t)__bfloat16_as_ushort(l1) << 16);
            }
            CP_WAIT0();
        }
        __syncthreads();
    }

    // ---- stage Y into smem (fragment layout -> row-major) ----
    float* Ys = (float*)smem;
#pragma unroll
    for (int mi = 0; mi < 2; mi++)
#pragma unroll
        for (int nj = 0; nj < 4; nj++) {
            int row = wm * 32 + mi * 16 + g;
            int col = wn * 32 + nj * 8 + 2 * t4;
            *(float2*)&Ys[row * YS_STRIDE + col]       = make_float2(d[mi][nj][0], d[mi][nj][1]);
            *(float2*)&Ys[(row + 8) * YS_STRIDE + col] = make_float2(d[mi][nj][2], d[mi][nj][3]);
        }
    float* Ws = (float*)(smem + OFF_WS);
    for (int i = tid; i < 64 * 64; i += 256) Ws[i] = weight[i];
    __syncthreads();

    // ---- Z = Y @ W (fp32 f32x2), BN partials, store (proven) ----
    const int tx = tid & 15;
    const int ty = tid >> 4;
    const unsigned long long z0 = pk2(0.f, 0.f);
    unsigned long long zp[8][2];
#pragma unroll
    for (int i = 0; i < 8; i++) { zp[i][0] = z0; zp[i][1] = z0; }

#pragma unroll 4
    for (int f = 0; f < 64; f++) {
        float4 w = *(const float4*)&Ws[f * 64 + tx * 4];
        unsigned long long w01 = pk2(w.x, w.y);
        unsigned long long w23 = pk2(w.z, w.w);
#pragma unroll
        for (int i = 0; i < 8; i++) {
            float yv = Ys[(ty * 8 + i) * YS_STRIDE + f];
            unsigned long long yy = pk2(yv, yv);
            zp[i][0] = ffma2(yy, w01, zp[i][0]);
            zp[i][1] = ffma2(yy, w23, zp[i][1]);
        }
    }

    float csum[4] = {0.f, 0.f, 0.f, 0.f};
    float csq[4]  = {0.f, 0.f, 0.f, 0.f};
#pragma unroll
    for (int i = 0; i < 8; i++) {
        float v0, v1, v2, v3;
        upk2(zp[i][0], v0, v1);
        upk2(zp[i][1], v2, v3);
        csum[0] += v0; csq[0] += v0 * v0;
        csum[1] += v1; csq[1] += v1 * v1;
        csum[2] += v2; csq[2] += v2 * v2;
        csum[3] += v3; csq[3] += v3 * v3;
        int gm = mt * 128 + ty * 8 + i;
        if (gm < N_NODES) {
            size_t o = (((size_t)b * N_NODES + gm) * N_T + t) * N_F + tx * 4;
            *(float4*)&out[o] = make_float4(v0, v1, v2, v3);
        }
    }

    __syncthreads();
    float* red = Ws;
    if (tid < 128) red[tid] = 0.f;
    __syncthreads();
#pragma unroll
    for (int j = 0; j < 4; j++) {
        atomicAdd(&red[tx * 4 + j], csum[j]);
        atomicAdd(&red[64 + tx * 4 + j], csq[j]);
    }
    __syncthreads();
    if (tid < 64) {
        int slab = (blockIdx.x + 3 * blockIdx.y) & 15;
        atomicAdd(&g_psum[slab][tid], red[tid]);
        atomicAdd(&g_psq[slab][tid],  red[64 + tid]);
    }
}

// ---------------- BN finalize + apply (proven) ----------------
__global__ void bn_finalize(const float* __restrict__ gamma, const float* __restrict__ beta) {
    int c = threadIdx.x;
    if (c >= N_F) return;
    float s = 0.f, q = 0.f;
    for (int i = 0; i < 16; i++) { s += g_psum[i][c]; q += g_psq[i][c]; }
    float inv  = 1.f / (float)COUNT_TOTAL;
    float mean = s * inv;
    float var  = q * inv - mean * mean;
    float sc   = gamma[c] * rsqrtf(var + 1e-5f);
    g_scale[c] = sc;
    g_shift[c] = beta[c] - mean * sc;
}

__global__ void bn_apply(float* __restrict__ out) {
    __shared__ float sc[N_F], sh[N_F];
    if (threadIdx.x < N_F) {
        sc[threadIdx.x] = g_scale[threadIdx.x];
        sh[threadIdx.x] = g_shift[threadIdx.x];
    }
    __syncthreads();
    size_t i = (size_t)blockIdx.x * blockDim.x + threadIdx.x;
    size_t e = i * 4;
    if (e >= (size_t)N_BATCH * N_NODES * N_T * N_F) return;
    int fb = (int)(e & 63);
    float4 v = *(const float4*)&out[e];
    float4 r;
    r.x = fmaxf(v.x * sc[fb + 0] + sh[fb + 0], 0.f);
    r.y = fmaxf(v.y * sc[fb + 1] + sh[fb + 1], 0.f);
    r.z = fmaxf(v.z * sc[fb + 2] + sh[fb + 2], 0.f);
    r.w = fmaxf(v.w * sc[fb + 3] + sh[fb + 3], 0.f);
    *(float4*)&out[e] = r;
}

extern "C" void kernel_launch(void* const* d_in, const int* in_sizes, int n_in,
                              void* d_out, int out_size) {
    const float *x = nullptr, *adj = nullptr, *w = nullptr, *gamma = nullptr, *beta = nullptr;
    for (int i = 0; i < n_in; i++) {
        int s = in_sizes[i];
        if      (s == N_BATCH * N_NODES * N_T * N_F) x   = (const float*)d_in[i];
        else if (s == N_NODES * N_NODES)             adj = (const float*)d_in[i];
        else if (s == N_F * N_F)                     w   = (const float*)d_in[i];
        else if (s == N_F) { if (!gamma) gamma = (const float*)d_in[i]; else beta = (const float*)d_in[i]; }
    }
    float* out = (float*)d_out;

    cudaFuncSetAttribute(gcn_mma, cudaFuncAttributeMaxDynamicSharedMemorySize, SMEM_TOTAL);

    prep_deg<<<1, 352>>>(adj);
    prep_at<<<(3 * NUM_KC * 128 * 40 + 255) / 256, 256>>>(adj);
    // mt fastest: the 3 m-tile blocks of one (b,t) share the X slice via L2;
    // A tiles (660KB x2) stay L2-resident across the whole launch.
    gcn_mma<<<dim3(3, 64, 32), 256, SMEM_TOTAL>>>(x, w, out);
    bn_finalize<<<1, 64>>>(gamma, beta);
    bn_apply<<<41600, 256>>>(out);
}